// round 2
// baseline (speedup 1.0000x reference)
#include <cuda_runtime.h>
#include <math.h>

// Shared-memory weight layout (floats). All vector-accessed blocks are
// 16B-aligned (offsets multiples of 4) and stored TRANSPOSED: wt[k*J + j]
// so the j-dimension is contiguous for float4 LDS.
#define OFF_GLOB_WT 0       // [57][32]
#define OFF_GLOB_B  1824    // [32]
#define OFF_AGGW    1856    // [32]
#define OFF_FC_WT   1888    // [32][16]
#define OFF_FC_B    2400    // [16]
#define OFF_LR0_WT  2416    // [24][64]
#define OFF_LR0_B   3952    // [64]
#define OFF_SIGMA_W 4016    // [64]
#define OFF_COL1_WT 4080    // [111][64]
#define OFF_COL1_B  11184   // [64]
#define OFF_COL2_W  11248   // [64]
#define OFF_VIEW_WT 11312   // [4][19]
#define OFF_VIEW_B  11388   // [19]
#define OFF_SC      11407   // aggw_b, sigma_b, col2_b
#define SH_TOTAL    11410

__device__ __forceinline__ void compute_ifr(const float* __restrict__ sp,
                                            const float* __restrict__ sh,
                                            float* ifr) {
    float d0 = sp[19], d1 = sp[20], d2 = sp[21], d3 = sp[22];
#pragma unroll
    for (int j = 0; j < 19; j++) {
        float v = sh[OFF_VIEW_B + j]
                + sh[OFF_VIEW_WT + 0 * 19 + j] * d0
                + sh[OFF_VIEW_WT + 1 * 19 + j] * d1
                + sh[OFF_VIEW_WT + 2 * 19 + j] * d2
                + sh[OFF_VIEW_WT + 3 * 19 + j] * d3;
        v = fmaxf(v, 0.0f);
        ifr[j] = sp[j] + v;
    }
}

__global__ void __launch_bounds__(128)
nerf_fused_kernel(const float* __restrict__ vox,
                  const float* __restrict__ ifrd,
                  const float* __restrict__ view_w, const float* __restrict__ view_b,
                  const float* __restrict__ glob_w, const float* __restrict__ glob_b,
                  const float* __restrict__ aggw_w, const float* __restrict__ aggw_b,
                  const float* __restrict__ fc_w,   const float* __restrict__ fc_b,
                  const float* __restrict__ lr0_w,  const float* __restrict__ lr0_b,
                  const float* __restrict__ sigma_w,const float* __restrict__ sigma_b,
                  const float* __restrict__ col1_w, const float* __restrict__ col1_b,
                  const float* __restrict__ col2_w, const float* __restrict__ col2_b,
                  float* __restrict__ out, int N) {
    __shared__ float sh[SH_TOTAL];

    // ---- stage + transpose weights into shared ----
    const int t = threadIdx.x;
    const int bs = blockDim.x;
    for (int idx = t; idx < 32 * 57; idx += bs) {
        int j = idx / 57, k = idx % 57;
        sh[OFF_GLOB_WT + k * 32 + j] = glob_w[idx];
    }
    for (int idx = t; idx < 32; idx += bs) {
        sh[OFF_GLOB_B + idx] = glob_b[idx];
        sh[OFF_AGGW + idx]   = aggw_w[idx];
    }
    for (int idx = t; idx < 16 * 32; idx += bs) {
        int j = idx / 32, k = idx % 32;
        sh[OFF_FC_WT + k * 16 + j] = fc_w[idx];
    }
    for (int idx = t; idx < 16; idx += bs) sh[OFF_FC_B + idx] = fc_b[idx];
    for (int idx = t; idx < 64 * 24; idx += bs) {
        int j = idx / 24, k = idx % 24;
        sh[OFF_LR0_WT + k * 64 + j] = lr0_w[idx];
    }
    for (int idx = t; idx < 64; idx += bs) {
        sh[OFF_LR0_B + idx]  = lr0_b[idx];
        sh[OFF_SIGMA_W + idx] = sigma_w[idx];
        sh[OFF_COL1_B + idx] = col1_b[idx];
        sh[OFF_COL2_W + idx] = col2_w[idx];
    }
    for (int idx = t; idx < 64 * 111; idx += bs) {
        int j = idx / 111, k = idx % 111;
        sh[OFF_COL1_WT + k * 64 + j] = col1_w[idx];
    }
    for (int idx = t; idx < 76; idx += bs) {
        int j = idx / 4, k = idx % 4;
        sh[OFF_VIEW_WT + k * 19 + j] = view_w[idx];
    }
    for (int idx = t; idx < 19; idx += bs) sh[OFF_VIEW_B + idx] = view_b[idx];
    if (t == 0) {
        sh[OFF_SC + 0] = aggw_b[0];
        sh[OFF_SC + 1] = sigma_b[0];
        sh[OFF_SC + 2] = col2_b[0];
    }
    __syncthreads();

    const int i = blockIdx.x * blockDim.x + threadIdx.x;
    if (i >= N) return;

    const float* row = ifrd + (size_t)i * 92;  // [4][23]

    // ================= Phase A: per-view feature stats =================
    float sum[19], sumsq[19];
#pragma unroll
    for (int j = 0; j < 19; j++) { sum[j] = 0.0f; sumsq[j] = 0.0f; }

#pragma unroll
    for (int s = 0; s < 4; s++) {
        const float* sp = row + s * 23;
        float ifr[19];
        compute_ifr(sp, sh, ifr);
#pragma unroll
        for (int j = 0; j < 19; j++) {
            sum[j] += ifr[j];
            sumsq[j] += ifr[j] * ifr[j];
        }
    }
    float avg[19], varr[19];
#pragma unroll
    for (int j = 0; j < 19; j++) {
        float m = sum[j] * 0.25f;
        avg[j] = m;
        varr[j] = (sumsq[j] - 4.0f * m * m) * (1.0f / 3.0f);
    }

    // ================= Phase B: global feat + online softmax agg =======
    float num[32];
#pragma unroll
    for (int j = 0; j < 32; j++) num[j] = 0.0f;
    float dsum = 0.0f, mmax = -1e30f;

    for (int s = 0; s < 4; s++) {
        const float* sp = row + s * 23;
        float ifr[19];
        compute_ifr(sp, sh, ifr);

        float gf[32];
#pragma unroll
        for (int j = 0; j < 32; j++) gf[j] = sh[OFF_GLOB_B + j];

#define GLOB_ACC(xval, krow)                                                     \
        {                                                                        \
            float xk = (xval);                                                   \
            const float4* w4 = reinterpret_cast<const float4*>(                  \
                &sh[OFF_GLOB_WT + (krow) * 32]);                                 \
            _Pragma("unroll")                                                    \
            for (int jq = 0; jq < 8; jq++) {                                     \
                float4 w = w4[jq];                                               \
                gf[4 * jq + 0] += w.x * xk;                                      \
                gf[4 * jq + 1] += w.y * xk;                                      \
                gf[4 * jq + 2] += w.z * xk;                                      \
                gf[4 * jq + 3] += w.w * xk;                                      \
            }                                                                    \
        }
#pragma unroll 4
        for (int k = 0; k < 19; k++) GLOB_ACC(ifr[k], k);
#pragma unroll 4
        for (int k = 0; k < 19; k++) GLOB_ACC(varr[k], 19 + k);
#pragma unroll 4
        for (int k = 0; k < 19; k++) GLOB_ACC(avg[k], 38 + k);
#undef GLOB_ACC

        float l = sh[OFF_SC + 0];
#pragma unroll
        for (int j = 0; j < 32; j++) {
            gf[j] = fmaxf(gf[j], 0.0f);
            l += sh[OFF_AGGW + j] * gf[j];
        }
        l = fmaxf(l, 0.0f);

        // online softmax accumulate
        if (l > mmax) {
            float c = __expf(mmax - l);
            dsum *= c;
#pragma unroll
            for (int j = 0; j < 32; j++) num[j] *= c;
            mmax = l;
        }
        float e = __expf(l - mmax);
        dsum += e;
#pragma unroll
        for (int j = 0; j < 32; j++) num[j] += gf[j] * e;
    }

    float im[32];
    {
        float inv = 1.0f / dsum;
#pragma unroll
        for (int j = 0; j < 32; j++) im[j] = num[j] * inv;
    }

    // ================= fc: 32 -> 16 =================
    float vif[24];
    {
        float img16[16];
#pragma unroll
        for (int j = 0; j < 16; j++) img16[j] = sh[OFF_FC_B + j];
#pragma unroll 4
        for (int k = 0; k < 32; k++) {
            float xk = im[k];
            const float4* w4 = reinterpret_cast<const float4*>(&sh[OFF_FC_WT + k * 16]);
#pragma unroll
            for (int jq = 0; jq < 4; jq++) {
                float4 w = w4[jq];
                img16[4 * jq + 0] += w.x * xk;
                img16[4 * jq + 1] += w.y * xk;
                img16[4 * jq + 2] += w.z * xk;
                img16[4 * jq + 3] += w.w * xk;
            }
        }
        const float* vp = vox + (size_t)i * 8;
#pragma unroll
        for (int k = 0; k < 8; k++) vif[k] = vp[k];
#pragma unroll
        for (int j = 0; j < 16; j++) vif[8 + j] = fmaxf(img16[j], 0.0f);
    }

    // ================= lr0: 24 -> 64 =================
    float x[64];
#pragma unroll
    for (int j = 0; j < 64; j++) x[j] = sh[OFF_LR0_B + j];
#pragma unroll 4
    for (int k = 0; k < 24; k++) {
        float xk = vif[k];
        const float4* w4 = reinterpret_cast<const float4*>(&sh[OFF_LR0_WT + k * 64]);
#pragma unroll
        for (int jq = 0; jq < 16; jq++) {
            float4 w = w4[jq];
            x[4 * jq + 0] += w.x * xk;
            x[4 * jq + 1] += w.y * xk;
            x[4 * jq + 2] += w.z * xk;
            x[4 * jq + 3] += w.w * xk;
        }
    }
#pragma unroll
    for (int j = 0; j < 64; j++) x[j] = fmaxf(x[j], 0.0f);

    // ================= sigma =================
    float sig;
    {
        float l = sh[OFF_SC + 1];
#pragma unroll
        for (int j = 0; j < 64; j++) l += sh[OFF_SIGMA_W + j] * x[j];
        // softplus (stable)
        sig = (l > 20.0f) ? l : log1pf(expf(l));
    }

    // ================= color branch: online softmax over views =========
    float cnum0 = 0.0f, cnum1 = 0.0f, cnum2 = 0.0f, cden = 0.0f, cmax = -1e30f;

    for (int s = 0; s < 4; s++) {
        const float* sp = row + s * 23;
        float f23[23];
#pragma unroll
        for (int k = 0; k < 23; k++) f23[k] = sp[k];

        float h[64];
#pragma unroll
        for (int j = 0; j < 64; j++) h[j] = sh[OFF_COL1_B + j];

#define COL_ACC(xval, krow)                                                      \
        {                                                                        \
            float xk = (xval);                                                   \
            const float4* w4 = reinterpret_cast<const float4*>(                  \
                &sh[OFF_COL1_WT + (krow) * 64]);                                 \
            _Pragma("unroll")                                                    \
            for (int jq = 0; jq < 16; jq++) {                                    \
                float4 w = w4[jq];                                               \
                h[4 * jq + 0] += w.x * xk;                                       \
                h[4 * jq + 1] += w.y * xk;                                       \
                h[4 * jq + 2] += w.z * xk;                                       \
                h[4 * jq + 3] += w.w * xk;                                       \
            }                                                                    \
        }
#pragma unroll 4
        for (int k = 0; k < 64; k++) COL_ACC(x[k], k);
#pragma unroll 4
        for (int k = 0; k < 24; k++) COL_ACC(vif[k], 64 + k);
#pragma unroll 4
        for (int k = 0; k < 23; k++) COL_ACC(f23[k], 88 + k);
#undef COL_ACC

        float l = sh[OFF_SC + 2];
#pragma unroll
        for (int j = 0; j < 64; j++) l += sh[OFF_COL2_W + j] * fmaxf(h[j], 0.0f);
        l = fmaxf(l, 0.0f);

        if (l > cmax) {
            float c = __expf(cmax - l);
            cnum0 *= c; cnum1 *= c; cnum2 *= c; cden *= c;
            cmax = l;
        }
        float e = __expf(l - cmax);
        cden += e;
        cnum0 += f23[16] * e;
        cnum1 += f23[17] * e;
        cnum2 += f23[18] * e;
    }

    float invd = 1.0f / cden;
    out[4 * (size_t)i + 0] = cnum0 * invd;
    out[4 * (size_t)i + 1] = cnum1 * invd;
    out[4 * (size_t)i + 2] = cnum2 * invd;
    out[4 * (size_t)i + 3] = sig;
}

extern "C" void kernel_launch(void* const* d_in, const int* in_sizes, int n_in,
                              void* d_out, int out_size) {
    const float* vox     = (const float*)d_in[0];
    const float* ifrd    = (const float*)d_in[1];
    const float* view_w  = (const float*)d_in[2];
    const float* view_b  = (const float*)d_in[3];
    const float* glob_w  = (const float*)d_in[4];
    const float* glob_b  = (const float*)d_in[5];
    const float* aggw_w  = (const float*)d_in[6];
    const float* aggw_b  = (const float*)d_in[7];
    const float* fc_w    = (const float*)d_in[8];
    const float* fc_b    = (const float*)d_in[9];
    const float* lr0_w   = (const float*)d_in[10];
    const float* lr0_b   = (const float*)d_in[11];
    const float* sigma_w = (const float*)d_in[12];
    const float* sigma_b = (const float*)d_in[13];
    const float* col1_w  = (const float*)d_in[14];
    const float* col1_b  = (const float*)d_in[15];
    const float* col2_w  = (const float*)d_in[16];
    const float* col2_b  = (const float*)d_in[17];
    float* out = (float*)d_out;

    int N = in_sizes[0] / 8;
    int threads = 128;
    int blocks = (N + threads - 1) / threads;
    nerf_fused_kernel<<<blocks, threads>>>(
        vox, ifrd, view_w, view_b, glob_w, glob_b, aggw_w, aggw_b,
        fc_w, fc_b, lr0_w, lr0_b, sigma_w, sigma_b, col1_w, col1_b,
        col2_w, col2_b, out, N);
}

// round 3
// speedup vs baseline: 1.7999x; 1.7999x over previous
#include <cuda_runtime.h>
#include <math.h>

// Shared-memory weight layout (floats). All vector-accessed blocks are
// 16B-aligned and stored TRANSPOSED: wt[k*J + j], j contiguous for float4 LDS.
#define OFF_GLOB_WT 0       // [57][32]
#define OFF_GLOB_B  1824    // [32]
#define OFF_AGGW    1856    // [32]
#define OFF_FC_WT   1888    // [32][16]
#define OFF_FC_B    2400    // [16]
#define OFF_LR0_WT  2416    // [24][64]
#define OFF_LR0_B   3952    // [64]
#define OFF_SIGMA_W 4016    // [64]
#define OFF_COL1_WT 4080    // [111][64]
#define OFF_COL1_B  11184   // [64]
#define OFF_COL2_W  11248   // [64]
#define OFF_VIEW_WT 11312   // [4][19]
#define OFF_VIEW_B  11388   // [19]
#define OFF_SC      11407   // aggw_b, sigma_b, col2_b
#define SH_TOTAL    11410

__global__ void __launch_bounds__(128)
nerf_fused_kernel(const float* __restrict__ vox,
                  const float* __restrict__ ifrd,
                  const float* __restrict__ view_w, const float* __restrict__ view_b,
                  const float* __restrict__ glob_w, const float* __restrict__ glob_b,
                  const float* __restrict__ aggw_w, const float* __restrict__ aggw_b,
                  const float* __restrict__ fc_w,   const float* __restrict__ fc_b,
                  const float* __restrict__ lr0_w,  const float* __restrict__ lr0_b,
                  const float* __restrict__ sigma_w,const float* __restrict__ sigma_b,
                  const float* __restrict__ col1_w, const float* __restrict__ col1_b,
                  const float* __restrict__ col2_w, const float* __restrict__ col2_b,
                  float* __restrict__ out, int N) {
    __shared__ float sh[SH_TOTAL];

    // ---- stage + transpose weights into shared ----
    const int t = threadIdx.x;
    const int bs = blockDim.x;
    for (int idx = t; idx < 32 * 57; idx += bs) {
        int j = idx / 57, k = idx % 57;
        sh[OFF_GLOB_WT + k * 32 + j] = glob_w[idx];
    }
    for (int idx = t; idx < 32; idx += bs) {
        sh[OFF_GLOB_B + idx] = glob_b[idx];
        sh[OFF_AGGW + idx]   = aggw_w[idx];
    }
    for (int idx = t; idx < 16 * 32; idx += bs) {
        int j = idx / 32, k = idx % 32;
        sh[OFF_FC_WT + k * 16 + j] = fc_w[idx];
    }
    for (int idx = t; idx < 16; idx += bs) sh[OFF_FC_B + idx] = fc_b[idx];
    for (int idx = t; idx < 64 * 24; idx += bs) {
        int j = idx / 24, k = idx % 24;
        sh[OFF_LR0_WT + k * 64 + j] = lr0_w[idx];
    }
    for (int idx = t; idx < 64; idx += bs) {
        sh[OFF_LR0_B + idx]   = lr0_b[idx];
        sh[OFF_SIGMA_W + idx] = sigma_w[idx];
        sh[OFF_COL1_B + idx]  = col1_b[idx];
        sh[OFF_COL2_W + idx]  = col2_w[idx];
    }
    for (int idx = t; idx < 64 * 111; idx += bs) {
        int j = idx / 111, k = idx % 111;
        sh[OFF_COL1_WT + k * 64 + j] = col1_w[idx];
    }
    for (int idx = t; idx < 76; idx += bs) {
        int j = idx / 4, k = idx % 4;
        sh[OFF_VIEW_WT + k * 19 + j] = view_w[idx];
    }
    for (int idx = t; idx < 19; idx += bs) sh[OFF_VIEW_B + idx] = view_b[idx];
    if (t == 0) {
        sh[OFF_SC + 0] = aggw_b[0];
        sh[OFF_SC + 1] = sigma_b[0];
        sh[OFF_SC + 2] = col2_b[0];
    }
    __syncthreads();

    const int i = blockIdx.x * blockDim.x + threadIdx.x;
    if (i >= N) return;

    const float* row = ifrd + (size_t)i * 92;  // [4][23]

    // ============ Phase A: compute ifr for all views once, + stats ============
    float ifr_all[4][19];
    float sum[19], sumsq[19];
#pragma unroll
    for (int j = 0; j < 19; j++) { sum[j] = 0.0f; sumsq[j] = 0.0f; }

#pragma unroll
    for (int s = 0; s < 4; s++) {
        const float* sp = row + s * 23;
        float d0 = sp[19], d1 = sp[20], d2 = sp[21], d3 = sp[22];
#pragma unroll
        for (int j = 0; j < 19; j++) {
            float v = sh[OFF_VIEW_B + j]
                    + sh[OFF_VIEW_WT + 0 * 19 + j] * d0
                    + sh[OFF_VIEW_WT + 1 * 19 + j] * d1
                    + sh[OFF_VIEW_WT + 2 * 19 + j] * d2
                    + sh[OFF_VIEW_WT + 3 * 19 + j] * d3;
            v = fmaxf(v, 0.0f);
            float f = sp[j] + v;
            ifr_all[s][j] = f;
            sum[j] += f;
            sumsq[j] += f * f;
        }
    }

#define ACCJ(arr, nJ, xval, base_off)                                            \
    {                                                                            \
        float xk = (xval);                                                       \
        const float4* w4 = reinterpret_cast<const float4*>(&sh[(base_off)]);     \
        _Pragma("unroll")                                                        \
        for (int jq = 0; jq < (nJ) / 4; jq++) {                                  \
            float4 w = w4[jq];                                                   \
            arr[4 * jq + 0] += w.x * xk;                                         \
            arr[4 * jq + 1] += w.y * xk;                                         \
            arr[4 * jq + 2] += w.z * xk;                                         \
            arr[4 * jq + 3] += w.w * xk;                                         \
        }                                                                        \
    }

    // ============ gf_base: bias + var rows + avg rows (view-invariant) ========
    float gf_base[32];
#pragma unroll
    for (int j = 0; j < 32; j++) gf_base[j] = sh[OFF_GLOB_B + j];
#pragma unroll 4
    for (int k = 0; k < 19; k++) {
        float m = sum[k] * 0.25f;
        float vr = (sumsq[k] - 4.0f * m * m) * (1.0f / 3.0f);
        ACCJ(gf_base, 32, vr, OFF_GLOB_WT + (19 + k) * 32);
        ACCJ(gf_base, 32, m,  OFF_GLOB_WT + (38 + k) * 32);
    }

    // ============ Phase B: per-view glob + online softmax agg ============
    float num[32];
#pragma unroll
    for (int j = 0; j < 32; j++) num[j] = 0.0f;
    float dsum = 0.0f, mmax = -1e30f;

#pragma unroll
    for (int s = 0; s < 4; s++) {
        float gf[32];
#pragma unroll
        for (int j = 0; j < 32; j++) gf[j] = gf_base[j];
#pragma unroll 4
        for (int k = 0; k < 19; k++) ACCJ(gf, 32, ifr_all[s][k], OFF_GLOB_WT + k * 32);

        float l = sh[OFF_SC + 0];
#pragma unroll
        for (int j = 0; j < 32; j++) {
            gf[j] = fmaxf(gf[j], 0.0f);
            l += sh[OFF_AGGW + j] * gf[j];
        }
        l = fmaxf(l, 0.0f);

        if (l > mmax) {
            float c = __expf(mmax - l);
            dsum *= c;
#pragma unroll
            for (int j = 0; j < 32; j++) num[j] *= c;
            mmax = l;
        }
        float e = __expf(l - mmax);
        dsum += e;
#pragma unroll
        for (int j = 0; j < 32; j++) num[j] += gf[j] * e;
    }

    // ============ fc: 32 -> 16, build vif[24] ============
    float vif[24];
    {
        float inv = 1.0f / dsum;
        float img16[16];
#pragma unroll
        for (int j = 0; j < 16; j++) img16[j] = sh[OFF_FC_B + j];
#pragma unroll 4
        for (int k = 0; k < 32; k++) ACCJ(img16, 16, num[k] * inv, OFF_FC_WT + k * 16);
        const float* vp = vox + (size_t)i * 8;
#pragma unroll
        for (int k = 0; k < 8; k++) vif[k] = vp[k];
#pragma unroll
        for (int j = 0; j < 16; j++) vif[8 + j] = fmaxf(img16[j], 0.0f);
    }

    // ============ lr0: 24 -> 64 ============
    float x[64];
#pragma unroll
    for (int j = 0; j < 64; j++) x[j] = sh[OFF_LR0_B + j];
#pragma unroll 4
    for (int k = 0; k < 24; k++) ACCJ(x, 64, vif[k], OFF_LR0_WT + k * 64);
#pragma unroll
    for (int j = 0; j < 64; j++) x[j] = fmaxf(x[j], 0.0f);

    // ============ sigma ============
    float sig;
    {
        float l = sh[OFF_SC + 1];
#pragma unroll
        for (int j = 0; j < 64; j++) l += sh[OFF_SIGMA_W + j] * x[j];
        sig = (l > 20.0f) ? l : log1pf(expf(l));
    }

    // ============ h_base: col1 rows 0..87 (view-invariant) ============
    float h_base[64];
#pragma unroll
    for (int j = 0; j < 64; j++) h_base[j] = sh[OFF_COL1_B + j];
#pragma unroll 4
    for (int k = 0; k < 64; k++) ACCJ(h_base, 64, x[k],   OFF_COL1_WT + k * 64);
#pragma unroll 4
    for (int k = 0; k < 24; k++) ACCJ(h_base, 64, vif[k], OFF_COL1_WT + (64 + k) * 64);

    // ============ color branch: per-view 23 rows + online softmax ============
    float cnum0 = 0.0f, cnum1 = 0.0f, cnum2 = 0.0f, cden = 0.0f, cmax = -1e30f;

#pragma unroll
    for (int s = 0; s < 4; s++) {
        const float* sp = row + s * 23;
        float f23[23];
#pragma unroll
        for (int k = 0; k < 23; k++) f23[k] = sp[k];

        float h[64];
#pragma unroll
        for (int j = 0; j < 64; j++) h[j] = h_base[j];
#pragma unroll 4
        for (int k = 0; k < 23; k++) ACCJ(h, 64, f23[k], OFF_COL1_WT + (88 + k) * 64);

        float l = sh[OFF_SC + 2];
#pragma unroll
        for (int j = 0; j < 64; j++) l += sh[OFF_COL2_W + j] * fmaxf(h[j], 0.0f);
        l = fmaxf(l, 0.0f);

        if (l > cmax) {
            float c = __expf(cmax - l);
            cnum0 *= c; cnum1 *= c; cnum2 *= c; cden *= c;
            cmax = l;
        }
        float e = __expf(l - cmax);
        cden += e;
        cnum0 += f23[16] * e;
        cnum1 += f23[17] * e;
        cnum2 += f23[18] * e;
    }

    float invd = 1.0f / cden;
    out[4 * (size_t)i + 0] = cnum0 * invd;
    out[4 * (size_t)i + 1] = cnum1 * invd;
    out[4 * (size_t)i + 2] = cnum2 * invd;
    out[4 * (size_t)i + 3] = sig;
}

extern "C" void kernel_launch(void* const* d_in, const int* in_sizes, int n_in,
                              void* d_out, int out_size) {
    const float* vox     = (const float*)d_in[0];
    const float* ifrd    = (const float*)d_in[1];
    const float* view_w  = (const float*)d_in[2];
    const float* view_b  = (const float*)d_in[3];
    const float* glob_w  = (const float*)d_in[4];
    const float* glob_b  = (const float*)d_in[5];
    const float* aggw_w  = (const float*)d_in[6];
    const float* aggw_b  = (const float*)d_in[7];
    const float* fc_w    = (const float*)d_in[8];
    const float* fc_b    = (const float*)d_in[9];
    const float* lr0_w   = (const float*)d_in[10];
    const float* lr0_b   = (const float*)d_in[11];
    const float* sigma_w = (const float*)d_in[12];
    const float* sigma_b = (const float*)d_in[13];
    const float* col1_w  = (const float*)d_in[14];
    const float* col1_b  = (const float*)d_in[15];
    const float* col2_w  = (const float*)d_in[16];
    const float* col2_b  = (const float*)d_in[17];
    float* out = (float*)d_out;

    int N = in_sizes[0] / 8;
    int threads = 128;
    int blocks = (N + threads - 1) / threads;
    nerf_fused_kernel<<<blocks, threads>>>(
        vox, ifrd, view_w, view_b, glob_w, glob_b, aggw_w, aggw_b,
        fc_w, fc_b, lr0_w, lr0_b, sigma_w, sigma_b, col1_w, col1_b,
        col2_w, col2_b, out, N);
}